// round 16
// baseline (speedup 1.0000x reference)
#include <cuda_runtime.h>
#include <cuda_bf16.h>

#define N 4096
#define THREADS 256
#define PPB 4                      /* pedestrians per block */
#define NBLOCKS (N / PPB)          /* 1024 */
#define ITERS 16                   /* per warp: 16 iters x 2 candidates/lane */
#define H_ITERS 8                  /* phase-1 subset: first half of the quarter */
#define GROUPS 4                   /* phase-3 gate granularity: 2 iters = 128 cands */
#define BUFCAP 64

typedef unsigned long long ull;
#define FULL 0xffffffffu
#define INFBITS 0x7f800000u

__device__ __forceinline__ ull umin64(ull a, ull b) { return a < b ? a : b; }

__global__ __launch_bounds__(THREADS)
void nn_tag_pool_kernel(const float* __restrict__ obs1,
                        const float* __restrict__ obs2,
                        const float* __restrict__ W,
                        const float* __restrict__ b,
                        float* __restrict__ out)
{
    __shared__ unsigned s_cnt[PPB];
    __shared__ unsigned s_vth[PPB];     // positive-float bits: uint order == float order
    __shared__ ull s_buf[PPB][BUFCAP];

    const int lane = threadIdx.x & 31;
    const int warp = threadIdx.x >> 5;
    const int pair    = warp >> 2;       // 0..1 : which ped-pair of this block
    const int quarter = warp & 3;        // 0..3 : which candidate quarter
    const int i0 = blockIdx.x * PPB + pair * 2;
    const int i1 = i0 + 1;

    if (threadIdx.x < PPB) { s_cnt[threadIdx.x] = 0; s_vth[threadIdx.x] = INFBITS; }
    __syncthreads();

    const float2* __restrict__ pos2 = (const float2*)obs2;
    const float4* __restrict__ pos4 = (const float4*)obs2;
    const float2 pa = __ldg(&pos2[i0]);
    const float2 pb = __ldg(&pos2[i1]);

    const float INF = __int_as_float(INFBITS);
    float a0 = INF, a1 = INF;   // ped A per-lane top-2 over the subset
    float b0 = INF, b1 = INF;   // ped B
    float gm[GROUPS] = {INF, INF, INF, INF};   // per-lane group minima (both peds)

    const int base4 = quarter * 512 + lane;   // float4 index: 512 per quarter

    // ---- Phase 1: scan the FIRST HALF of this quarter (512 cands); exact
    // keep-2 per lane over its 16 candidates. Threshold from a subset is a
    // valid upper bound on the global 5th (subset order stats >= full-set).
    // Self is in quarter 0's first half (dd == 1.0 exactly, global min).
    #pragma unroll 8
    for (int t = 0; t < H_ITERS; t++) {
        const float4 p = __ldg(&pos4[base4 + t * 32]);
        float loA, loB;
        {   float dx0 = p.x - pa.x, dy0 = p.y - pa.y;
            float ta = fmaf(dx0, dx0, fmaf(dy0, dy0, 1.0f));
            float dx1 = p.z - pa.x, dy1 = p.w - pa.y;
            float tb = fmaf(dx1, dx1, fmaf(dy1, dy1, 1.0f));
            float lo = fminf(ta, tb), hi = fmaxf(ta, tb);
            float m = fmaxf(a0, lo);
            a0 = fminf(a0, lo);
            a1 = fminf(fminf(a1, hi), m);
            loA = lo; }
        {   float dx0 = p.x - pb.x, dy0 = p.y - pb.y;
            float ta = fmaf(dx0, dx0, fmaf(dy0, dy0, 1.0f));
            float dx1 = p.z - pb.x, dy1 = p.w - pb.y;
            float tb = fmaf(dx1, dx1, fmaf(dy1, dy1, 1.0f));
            float lo = fminf(ta, tb), hi = fmaxf(ta, tb);
            float m = fmaxf(b0, lo);
            b0 = fminf(b0, lo);
            b1 = fminf(fminf(b1, hi), m);
            loB = lo; }
        gm[t >> 1] = fminf(gm[t >> 1], fminf(loA, loB));
    }

    // ---- Phase 2: retained-5th for A and B (interleaved); combine via atomicMin.
    // T >= 5th-smallest of the scanned subset >= global 5th (incl. self):
    // the filter below is exhaustive for the true top-4 + self.
    {
        unsigned eA0 = __float_as_uint(a0), eA1 = __float_as_uint(a1);
        unsigned eB0 = __float_as_uint(b0), eB1 = __float_as_uint(b1);
        unsigned mA = INFBITS, mB = INFBITS;
        #pragma unroll
        for (int r = 0; r < 5; r++) {
            mA = __reduce_min_sync(FULL, eA0);
            mB = __reduce_min_sync(FULL, eB0);
            unsigned balA = __ballot_sync(FULL, eA0 == mA);
            unsigned balB = __ballot_sync(FULL, eB0 == mB);
            if (lane == __ffs(balA) - 1) { eA0 = eA1; eA1 = INFBITS; }
            if (lane == __ffs(balB) - 1) { eB0 = eB1; eB1 = INFBITS; }
        }
        if (lane == 0) {
            atomicMin(&s_vth[pair * 2 + 0], mA);
            atomicMin(&s_vth[pair * 2 + 1], mB);
        }
    }
    __syncthreads();
    const float vthA = __uint_as_float(s_vth[pair * 2 + 0]);
    const float vthB = __uint_as_float(s_vth[pair * 2 + 1]);
    const float vmax = fmaxf(vthA, vthB);

    // ---- Phase 3a: gated rescan of the first half (group minima are exact:
    // bit-identical math -> nothing admissible hides in a skipped group).
    #pragma unroll
    for (int g = 0; g < GROUPS; g++) {
        if (__any_sync(FULL, gm[g] <= vmax)) {       // rare, warp-uniform
            #pragma unroll
            for (int tt = 0; tt < 2; tt++) {
                const int t = g * 2 + tt;
                const float4 p = __ldg(&pos4[base4 + t * 32]);
                const unsigned j0 = (unsigned)((base4 + t * 32) * 2);
                float dxA0 = p.x - pa.x, dyA0 = p.y - pa.y;
                float tA0 = fmaf(dxA0, dxA0, fmaf(dyA0, dyA0, 1.0f));
                float dxA1 = p.z - pa.x, dyA1 = p.w - pa.y;
                float tA1 = fmaf(dxA1, dxA1, fmaf(dyA1, dyA1, 1.0f));
                float dxB0 = p.x - pb.x, dyB0 = p.y - pb.y;
                float tB0 = fmaf(dxB0, dxB0, fmaf(dyB0, dyB0, 1.0f));
                float dxB1 = p.z - pb.x, dyB1 = p.w - pb.y;
                float tB1 = fmaf(dxB1, dxB1, fmaf(dyB1, dyB1, 1.0f));
                if (tA0 <= vthA) {
                    unsigned s = atomicAdd(&s_cnt[pair * 2 + 0], 1u);
                    if (s < BUFCAP) s_buf[pair * 2 + 0][s] = (((ull)__float_as_uint(tA0)) << 32) | j0;
                }
                if (tA1 <= vthA) {
                    unsigned s = atomicAdd(&s_cnt[pair * 2 + 0], 1u);
                    if (s < BUFCAP) s_buf[pair * 2 + 0][s] = (((ull)__float_as_uint(tA1)) << 32) | (j0 + 1);
                }
                if (tB0 <= vthB) {
                    unsigned s = atomicAdd(&s_cnt[pair * 2 + 1], 1u);
                    if (s < BUFCAP) s_buf[pair * 2 + 1][s] = (((ull)__float_as_uint(tB0)) << 32) | j0;
                }
                if (tB1 <= vthB) {
                    unsigned s = atomicAdd(&s_cnt[pair * 2 + 1], 1u);
                    if (s < BUFCAP) s_buf[pair * 2 + 1][s] = (((ull)__float_as_uint(tB1)) << 32) | (j0 + 1);
                }
            }
        }
    }

    // ---- Phase 3b: first full scan of the second half; compute + vote-gated append.
    #pragma unroll 4
    for (int t = H_ITERS; t < ITERS; t++) {
        const float4 p = __ldg(&pos4[base4 + t * 32]);
        float dxA0 = p.x - pa.x, dyA0 = p.y - pa.y;
        float tA0 = fmaf(dxA0, dxA0, fmaf(dyA0, dyA0, 1.0f));
        float dxA1 = p.z - pa.x, dyA1 = p.w - pa.y;
        float tA1 = fmaf(dxA1, dxA1, fmaf(dyA1, dyA1, 1.0f));
        float dxB0 = p.x - pb.x, dyB0 = p.y - pb.y;
        float tB0 = fmaf(dxB0, dxB0, fmaf(dyB0, dyB0, 1.0f));
        float dxB1 = p.z - pb.x, dyB1 = p.w - pb.y;
        float tB1 = fmaf(dxB1, dxB1, fmaf(dyB1, dyB1, 1.0f));
        float g2 = fminf(fminf(tA0, tA1), fminf(tB0, tB1));
        if (__any_sync(FULL, g2 <= vmax)) {          // warp-uniform, rare
            const unsigned j0 = (unsigned)((base4 + t * 32) * 2);
            if (tA0 <= vthA) {
                unsigned s = atomicAdd(&s_cnt[pair * 2 + 0], 1u);
                if (s < BUFCAP) s_buf[pair * 2 + 0][s] = (((ull)__float_as_uint(tA0)) << 32) | j0;
            }
            if (tA1 <= vthA) {
                unsigned s = atomicAdd(&s_cnt[pair * 2 + 0], 1u);
                if (s < BUFCAP) s_buf[pair * 2 + 0][s] = (((ull)__float_as_uint(tA1)) << 32) | (j0 + 1);
            }
            if (tB0 <= vthB) {
                unsigned s = atomicAdd(&s_cnt[pair * 2 + 1], 1u);
                if (s < BUFCAP) s_buf[pair * 2 + 1][s] = (((ull)__float_as_uint(tB0)) << 32) | j0;
            }
            if (tB1 <= vthB) {
                unsigned s = atomicAdd(&s_cnt[pair * 2 + 1], 1u);
                if (s < BUFCAP) s_buf[pair * 2 + 1][s] = (((ull)__float_as_uint(tB1)) << 32) | (j0 + 1);
            }
        }
    }
    __syncthreads();

    // ---- Phase 4 + epilogue: warps 0..3 each finish one pedestrian.
    // Up to 64 buffered entries: two u64 composite keys per lane, 4-round
    // shuffle-tree min extraction (lower-index tie-break preserved).
    if (warp < PPB) {
        const int ip = blockIdx.x * PPB + warp;
        unsigned n = s_cnt[warp]; if (n > BUFCAP) n = BUFCAP;
        ull e0 = ((unsigned)lane < n)        ? s_buf[warp][lane]      : ~0ull;
        ull e1 = ((unsigned)(lane + 32) < n) ? s_buf[warp][lane + 32] : ~0ull;
        // exclude self: its distance is bit-exactly 1.0f
        const ull selfkey = (((ull)0x3f800000u) << 32) | (unsigned)ip;
        if (e0 == selfkey) e0 = ~0ull;
        if (e1 == selfkey) e1 = ~0ull;

        const int kk = lane >> 3;   // neighbor rank for this lane
        const int o  = lane & 7;    // output channel for this lane
        unsigned nb = 0;
        #pragma unroll
        for (int r = 0; r < 4; r++) {
            ull my = umin64(e0, e1);
            ull k = my;
            #pragma unroll
            for (int off = 16; off; off >>= 1)
                k = umin64(k, __shfl_xor_sync(FULL, k, off));
            if (kk == r) nb = (unsigned)(k & 0xffffffffull);
            // pop exactly one: keys are unique (distinct idx in low bits)
            if (e0 == k) e0 = ~0ull;
            else if (e1 == k) e1 = ~0ull;
        }
        nb &= (N - 1);   // memory safety (only reachable on overflow)

        const float2* __restrict__ o1 = (const float2*)obs1;
        const float2 pp = __ldg(&pos2[ip]);
        const float2 pn = __ldg(&pos2[nb]);
        const float2 qi = __ldg(&o1[ip]);
        const float2 qn = __ldg(&o1[nb]);
        const float px = pn.x - pp.x;
        const float py = pn.y - pp.y;
        const float vx = (pn.x - qn.x) - (pp.x - qi.x);
        const float vy = (pn.y - qn.y) - (pp.y - qi.y);

        const float w0 = __ldg(&W[o * 6 + 0]);
        const float w1 = __ldg(&W[o * 6 + 1]);
        const float w2 = __ldg(&W[o * 6 + 2]);
        const float w3 = __ldg(&W[o * 6 + 3]);
        const float w4 = __ldg(&W[o * 6 + 4]);
        const float w5 = __ldg(&W[o * 6 + 5]);

        float e = __ldg(&b[o]) + w2 + w5 + w0 * px + w1 * py + w3 * vx + w4 * vy;
        out[ip * 32 + lane] = fmaxf(e, 0.0f);   // coalesced 128B store per warp
    }
}

extern "C" void kernel_launch(void* const* d_in, const int* in_sizes, int n_in,
                              void* d_out, int out_size)
{
    const float* obs1 = (const float*)d_in[0];
    const float* obs2 = (const float*)d_in[1];
    const float* W    = (const float*)d_in[2];
    const float* b    = (const float*)d_in[3];
    float* out = (float*)d_out;

    nn_tag_pool_kernel<<<NBLOCKS, THREADS>>>(obs1, obs2, W, b, out);
}